// round 14
// baseline (speedup 1.0000x reference)
#include <cuda_runtime.h>
#include <math.h>
#include <stdint.h>

#define KNUM 512
#define DDIM 64
#define NROWS 65536
#define HW 4096
#define NB 16
#define MTILE 128
#define NTILES 512
#define THREADS 512
#define CAP 24

typedef unsigned long long ull;

// ---------------- device scratch ----------------
__device__ double g_loss_sum;
__device__ unsigned int g_counts[KNUM];
__device__ unsigned int g_done;
__device__ float ssq_g[KNUM];
__device__ float invsk_g[KNUM];
__device__ unsigned int g_SeMax_bits;     // zero-init; monotone atomicMax (idempotent across replays)
__device__ unsigned int g_invskMax_bits;
// s8 B fragments, word-major: bfrag_s8_g[w*2048 + k*4 + q], w in [0,4)
// word w = 4 s8 of code k at dims w*16 + q*4 .. +3
__device__ uint32_t bfrag_s8_g[4 * KNUM * 4];

// ---------------- smem layout (bytes): total 85056 -> 2 CTAs/SM -------------
#define BS8_OFF   0        // 32768
#define XS_OFF    32768    // 32768  x_s[c*128+row]
#define SSQ_OFF   65536    // 2048
#define INVSK_OFF 67584    // 2048
#define SX_OFF    69632    // 512
#define SRINV_OFF 70144    // 512
#define MRG_OFF   70656    // 512
#define CL_OFF    71168    // 128*CAP*4 = 12288 (reused as double[512] in finalize)
#define CC_OFF    83456    // 512
#define SLOT_OFF  83968    // 1024
#define WS_OFF    84992    // 64
#define SMEM_TOTAL 85056
#define ZSEL_OFF  BS8_OFF  // overlays dead B region after rescue: 64*128 f32 = 32768

__device__ __forceinline__ void imma16832(int d[4], const uint32_t a[4],
                                          uint32_t b0, uint32_t b1) {
    asm volatile(
        "mma.sync.aligned.m16n8k32.row.col.s32.s8.s8.s32 "
        "{%0,%1,%2,%3}, {%4,%5,%6,%7}, {%8,%9}, {%0,%1,%2,%3};"
        : "+r"(d[0]), "+r"(d[1]), "+r"(d[2]), "+r"(d[3])
        : "r"(a[0]), "r"(a[1]), "r"(a[2]), "r"(a[3]), "r"(b0), "r"(b1));
}

__device__ __forceinline__ uint32_t pack_s8x4(int v0, int v1, int v2, int v3) {
    return (uint32_t)(v0 & 255) | ((uint32_t)(v1 & 255) << 8) |
           ((uint32_t)(v2 & 255) << 16) | ((uint32_t)(v3 & 255) << 24);
}

// ---------------- prep: exact ssq + s8 quantized codebook -------------------
__global__ void vq_prep_kernel(const float* __restrict__ emb) {
    const int k = blockIdx.x;
    const int t = threadIdx.x;
    if (t == 0) {
        g_counts[k] = 0u;
        if (k == 0) { g_loss_sum = 0.0; g_done = 0u; }
        const float* e = emb + k * DDIM;
        float s = 0.f;
        for (int d = 0; d < DDIM; d++)
            s = __fadd_rn(s, __fmul_rn(e[d], e[d]));   // reference order (unfused)
        ssq_g[k] = s;
    }
    // per-code max|e|
    float a = fmaxf(fabsf(emb[k * DDIM + t]), fabsf(emb[k * DDIM + 32 + t]));
    #pragma unroll
    for (int o = 16; o > 0; o >>= 1)
        a = fmaxf(a, __shfl_xor_sync(0xffffffffu, a, o));
    float maxe  = fmaxf(a, 1e-30f);
    float sk    = 127.f / maxe;
    float invsk = maxe * (1.f / 127.f);
    // quantize + pack (threads 0..15: w = t>>2, q = t&3)
    int sabs = 0;
    if (t < 16) {
        int w = t >> 2, q = t & 3;
        int d0 = w * 16 + q * 4;
        int v[4];
        #pragma unroll
        for (int j = 0; j < 4; j++) {
            v[j] = __float2int_rn(emb[k * DDIM + d0 + j] * sk);
            sabs += abs(v[j]);
        }
        bfrag_s8_g[w * (KNUM * 4) + k * 4 + q] = pack_s8x4(v[0], v[1], v[2], v[3]);
    }
    #pragma unroll
    for (int o = 16; o > 0; o >>= 1)
        sabs += __shfl_xor_sync(0xffffffffu, sabs, o);
    if (t == 0) {
        invsk_g[k] = invsk;
        float Se = (float)sabs * invsk;           // sum |e_hat|
        atomicMax(&g_SeMax_bits, __float_as_uint(Se));
        atomicMax(&g_invskMax_bits, __float_as_uint(invsk));
    }
}

// ---------------- exact rescue evaluation (bit-exact reference pipeline) ----
__device__ __forceinline__ void eval_exact(int k, int row, const float* emb,
                                           const float* x_s, const float* sx_s,
                                           const float* ssq_s, ull* slot) {
    const float4* eg = (const float4*)(emb + k * DDIM);
    float acc = 0.f;
    #pragma unroll
    for (int i = 0; i < 16; i++) {
        float4 e = eg[i];
        acc = fmaf(x_s[(4 * i + 0) * 128 + row], e.x, acc);
        acc = fmaf(x_s[(4 * i + 1) * 128 + row], e.y, acc);
        acc = fmaf(x_s[(4 * i + 2) * 128 + row], e.z, acc);
        acc = fmaf(x_s[(4 * i + 3) * 128 + row], e.w, acc);
    }
    float d = __fadd_rn(sx_s[row], ssq_s[k]);
    d = __fsub_rn(d, __fmul_rn(2.0f, acc));
    uint32_t ui = __float_as_uint(d);
    uint32_t key = ui ^ ((ui & 0x80000000u) ? 0xFFFFFFFFu : 0x80000000u);
    atomicMin(&slot[row], ((ull)key << 32) | (uint32_t)k);
}

// ---------------- main (finalize fused via last-CTA) ------------------------
extern __shared__ char smem[];

__global__ __launch_bounds__(THREADS, 2)
void vq_main_kernel(const float* __restrict__ z_e,
                    const float* __restrict__ emb,
                    float* __restrict__ zq_out,
                    float* __restrict__ idx_out,
                    float* __restrict__ loss_out,
                    float* __restrict__ perp_out)
{
    const int tid  = threadIdx.x;
    const int wid  = tid >> 5;
    const int lane = tid & 31;
    const int wq   = lane & 3;
    const int wr   = lane >> 2;
    const int tile = blockIdx.x;
    const int n    = tile >> 5;
    const int hw0  = (tile & 31) * MTILE;
    const size_t gbase = (size_t)n * (DDIM * HW) + hw0;

    float* x_s     = (float*)(smem + XS_OFF);
    float* ssq_s   = (float*)(smem + SSQ_OFF);
    float* invsk_s = (float*)(smem + INVSK_OFF);
    float* sx_s    = (float*)(smem + SX_OFF);
    float* srinv_s = (float*)(smem + SRINV_OFF);
    float* mrg_s   = (float*)(smem + MRG_OFF);
    uint32_t* clist = (uint32_t*)(smem + CL_OFF);
    uint32_t* ccnt  = (uint32_t*)(smem + CC_OFF);
    ull*   slot    = (ull*)(smem + SLOT_OFF);
    float* wsum    = (float*)(smem + WS_OFF);
    const uint32_t* sB = (const uint32_t*)(smem + BS8_OFF);
    __shared__ int s_final;

    if (tid < MTILE) { slot[tid] = ~0ull; ccnt[tid] = 0u; }

    // Stage s8 B fragments (32 KB) + per-code scalars
    {
        const uint4* gh = (const uint4*)bfrag_s8_g;
        uint4* sh = (uint4*)(smem + BS8_OFF);
        for (int i = tid; i < 4 * KNUM; i += THREADS) sh[i] = gh[i];
    }
    ssq_s[tid]   = ssq_g[tid];
    invsk_s[tid] = invsk_g[tid];
    // x tile (coalesced) -> x_s[c*128+row]
    for (int i = tid; i < MTILE * DDIM; i += THREADS) {
        int c = i >> 7, r = i & 127;
        x_s[c * 128 + r] = z_e[gbase + (size_t)c * HW + r];
    }
    __syncthreads();

    // per-row: exact ||x||^2 (reference order) + max|x| + sum|x| -> margin
    if (tid < MTILE) {
        const float SeMax    = __uint_as_float(g_SeMax_bits);
        const float invSkMax = __uint_as_float(g_invskMax_bits);
        float s = 0.f, mx = 1e-30f, sa = 0.f;
        for (int c = 0; c < DDIM; c++) {
            float xv = x_s[c * 128 + tid];
            s = __fadd_rn(s, __fmul_rn(xv, xv));
            float av = fabsf(xv);
            mx = fmaxf(mx, av);
            sa += av;
        }
        sx_s[tid] = s;
        float srinv = mx * (1.f / 127.f);
        srinv_s[tid] = srinv;
        mrg_s[tid] = srinv * SeMax + invSkMax * sa + 5e-5f;
    }
    __syncthreads();

    // s8 A fragments for this warp's 16 rows (rA, rB), both k-halves
    const int r0   = (wid & 7) * 16;
    const int half = wid >> 3;
    const int rA = r0 + wr, rB = rA + 8;
    const float srA = 127.f / (srinv_s[rA] * 127.f * 127.f) * 127.f; // == 1/srinv (see below)
    // (compute directly to avoid precision weirdness:)
    const float srAq = 127.f / fmaxf(srinv_s[rA] * 127.f, 1e-30f);
    const float srBq = 127.f / fmaxf(srinv_s[rB] * 127.f, 1e-30f);
    uint32_t aq[2][4];
    #pragma unroll
    for (int kh = 0; kh < 2; kh++) {
        #pragma unroll
        for (int hh = 0; hh < 2; hh++) {   // hh: k sub-half (0: +0, 1: +16)
            int d0 = kh * 32 + hh * 16 + wq * 4;
            int vA[4], vB[4];
            #pragma unroll
            for (int j = 0; j < 4; j++) {
                vA[j] = __float2int_rn(x_s[(d0 + j) * 128 + rA] * srAq);
                vB[j] = __float2int_rn(x_s[(d0 + j) * 128 + rB] * srBq);
            }
            aq[kh][hh * 2 + 0] = pack_s8x4(vA[0], vA[1], vA[2], vA[3]);
            aq[kh][hh * 2 + 1] = pack_s8x4(vB[0], vB[1], vB[2], vB[3]);
        }
    }
    // a-register order for m16n8k32: {rowG k0..3, rowG+8 k0..3, rowG k16..19, rowG+8 k16..19}
    // our aq[kh] = {rA @ +0, rB @ +0, rA @ +16, rB @ +16}  -- matches.

    const float srinvA = srinv_s[rA], srinvB = srinv_s[rB];
    const float mrgA = mrg_s[rA], mrgB = mrg_s[rB];

    // IMMA filter: 8 groups of 32 cols
    float m0 = 3.4e38f, m1 = 3.4e38f;
    for (int g = 0; g < 8; g++) {
        int acc[4][4];
        #pragma unroll
        for (int nf = 0; nf < 4; nf++)
            #pragma unroll
            for (int j = 0; j < 4; j++) acc[nf][j] = 0;

        const int colbase0 = half * 256 + g * 32;
        #pragma unroll
        for (int nf = 0; nf < 4; nf++) {
            int bi = ((colbase0 + nf * 8 + wr) << 2) + wq;  // bank = lane, conflict-free
            uint32_t b0 = sB[0 * 2048 + bi], b1 = sB[1 * 2048 + bi];
            uint32_t b2 = sB[2 * 2048 + bi], b3 = sB[3 * 2048 + bi];
            imma16832(acc[nf], aq[0], b0, b1);
            imma16832(acc[nf], aq[1], b2, b3);
        }
        float dv[4][4];
        #pragma unroll
        for (int nf = 0; nf < 4; nf++) {
            int c0 = colbase0 + nf * 8 + wq * 2;
            float f0 = (float)acc[nf][0] * (srinvA * invsk_s[c0]);
            float f1 = (float)acc[nf][1] * (srinvA * invsk_s[c0 + 1]);
            float f2 = (float)acc[nf][2] * (srinvB * invsk_s[c0]);
            float f3 = (float)acc[nf][3] * (srinvB * invsk_s[c0 + 1]);
            dv[nf][0] = fmaf(f0, -2.f, ssq_s[c0]);
            dv[nf][1] = fmaf(f1, -2.f, ssq_s[c0 + 1]);
            dv[nf][2] = fmaf(f2, -2.f, ssq_s[c0]);
            dv[nf][3] = fmaf(f3, -2.f, ssq_s[c0 + 1]);
            m0 = fminf(m0, fminf(dv[nf][0], dv[nf][1]));
            m1 = fminf(m1, fminf(dv[nf][2], dv[nf][3]));
        }
        m0 = fminf(m0, __shfl_xor_sync(0xffffffffu, m0, 1));
        m0 = fminf(m0, __shfl_xor_sync(0xffffffffu, m0, 2));
        m1 = fminf(m1, __shfl_xor_sync(0xffffffffu, m1, 1));
        m1 = fminf(m1, __shfl_xor_sync(0xffffffffu, m1, 2));
        float t0 = m0 + mrgA, t1 = m1 + mrgB;
        #pragma unroll
        for (int nf = 0; nf < 4; nf++) {
            int c0 = colbase0 + nf * 8 + wq * 2;
            if (dv[nf][0] <= t0) { uint32_t c = atomicAdd(&ccnt[rA], 1u); if (c < CAP) clist[rA * CAP + c] = c0; }
            if (dv[nf][1] <= t0) { uint32_t c = atomicAdd(&ccnt[rA], 1u); if (c < CAP) clist[rA * CAP + c] = c0 + 1; }
            if (dv[nf][2] <= t1) { uint32_t c = atomicAdd(&ccnt[rB], 1u); if (c < CAP) clist[rB * CAP + c] = c0; }
            if (dv[nf][3] <= t1) { uint32_t c = atomicAdd(&ccnt[rB], 1u); if (c < CAP) clist[rB * CAP + c] = c0 + 1; }
        }
    }
    __syncthreads();

    // Rescue: exact re-evaluation of listed candidates (4 threads per row)
    {
        int row = tid >> 2, e0 = tid & 3;
        int cnt = (int)ccnt[row];
        if (cnt <= CAP) {
            for (int i = e0; i < cnt; i += 4)
                eval_exact((int)clist[row * CAP + i], row, emb, x_s, sx_s, ssq_s, slot);
        } else {
            for (int k = e0; k < KNUM; k += 4)   // guaranteed-correct fallback
                eval_exact(k, row, emb, x_s, sx_s, ssq_s, slot);
        }
    }
    __syncthreads();

    // Stage selected codes into smem (overlays dead B region)
    float* zsel = (float*)(smem + ZSEL_OFF);
    if (tid < MTILE) {
        int kk = (int)(uint32_t)(slot[tid] & 0xFFFFFFFFull);
        const float4* eg = (const float4*)(emb + kk * DDIM);
        #pragma unroll
        for (int i = 0; i < 16; i++) {
            float4 e = eg[i];
            zsel[(4 * i + 0) * 128 + tid] = e.x;
            zsel[(4 * i + 1) * 128 + tid] = e.y;
            zsel[(4 * i + 2) * 128 + tid] = e.z;
            zsel[(4 * i + 3) * 128 + tid] = e.w;
        }
        if (idx_out) idx_out[tile * MTILE + tid] = (float)kk;
        atomicAdd(&g_counts[kk], 1u);
    }
    __syncthreads();

    // z_q straight-through + commitment loss partial
    float lsum = 0.f;
    for (int i = tid; i < MTILE * DDIM; i += THREADS) {
        int c = i >> 7, r = i & 127;
        float v  = zsel[c * 128 + r];
        float xv = x_s[c * 128 + r];
        float diff = __fsub_rn(v, xv);
        zq_out[gbase + (size_t)c * HW + r] = __fadd_rn(xv, diff);
        lsum = fmaf(diff, diff, lsum);
    }
    #pragma unroll
    for (int o = 16; o > 0; o >>= 1)
        lsum += __shfl_down_sync(0xffffffffu, lsum, o);
    if (lane == 0) wsum[wid] = lsum;
    __syncthreads();
    if (tid == 0) {
        float t = 0.f;
        #pragma unroll
        for (int w = 0; w < THREADS / 32; w++) t += wsum[w];
        atomicAdd(&g_loss_sum, (double)t);
    }

    // ---- fused finalize: last CTA computes loss & perplexity ----
    __threadfence();
    if (tid == 0) {
        unsigned r = atomicAdd(&g_done, 1u);
        s_final = (r == NTILES - 1) ? 1 : 0;
    }
    __syncthreads();
    if (s_final) {
        double* sh = (double*)(smem + CL_OFF);
        double c = (double)g_counts[tid];
        double p = c / (double)NROWS;
        sh[tid] = p * log(p + 1e-10);
        __syncthreads();
        for (int s = KNUM / 2; s > 0; s >>= 1) {
            if (tid < s) sh[tid] += sh[tid + s];
            __syncthreads();
        }
        if (tid == 0) {
            if (perp_out) *perp_out = (float)exp(-sh[0]);
            if (loss_out) *loss_out = (float)(0.25 * g_loss_sum / (double)((size_t)NROWS * DDIM));
        }
    }
}

extern "C" void kernel_launch(void* const* d_in, const int* in_sizes, int n_in,
                              void* d_out, int out_size) {
    const float* z_e = (const float*)d_in[0];
    const float* emb = (const float*)d_in[1];
    float* out = (float*)d_out;

    float* zq_out = out;
    float* loss_p = nullptr;
    float* perp_p = nullptr;
    float* idx_p  = nullptr;
    const int ZQ = NB * DDIM * HW;   // 4194304
    if (out_size >= ZQ + 2 + NROWS) {
        loss_p = out + ZQ;
        perp_p = out + ZQ + 1;
        idx_p  = out + ZQ + 2;
    }

    cudaFuncSetAttribute(vq_main_kernel,
                         cudaFuncAttributeMaxDynamicSharedMemorySize, SMEM_TOTAL);

    vq_prep_kernel<<<KNUM, 32>>>(emb);
    vq_main_kernel<<<NTILES, THREADS, SMEM_TOTAL>>>(z_e, emb, zq_out, idx_p, loss_p, perp_p);
}

// round 15
// speedup vs baseline: 1.0398x; 1.0398x over previous
#include <cuda_runtime.h>
#include <math.h>
#include <stdint.h>

#define KNUM 512
#define DDIM 64
#define NROWS 65536
#define HW 4096
#define NB 16
#define MTILE 128
#define NTILES 512
#define THREADS 512
#define GRID 296
#define CAP 24

typedef unsigned long long ull;

// ---------------- device scratch ----------------
__device__ double g_loss_sum;
__device__ unsigned int g_counts[KNUM];
__device__ unsigned int g_done;
__device__ unsigned int g_ticket;
__device__ float ssq_g[KNUM];
__device__ unsigned int g_maxE_bits;    // monotone atomicMax, idempotent across replays
__device__ unsigned int g_SeMax_bits;
__device__ float g_S;
// paired s8 B fragments: bpack_g[p][(k*4+q)*2+h]; p=0 covers k-dims 0..31, p=1: 32..63
__device__ uint32_t bpack_g[2][KNUM * 8];

// ---------------- smem layout (bytes): total 83520 -> 2 CTAs/SM ------------
#define B0_OFF   0        // 16384
#define B1_OFF   16384    // 16384
#define XS_OFF   32768    // 32768  x_s[c*128+row]
#define SSQ_OFF  65536    // 2048
#define SX_OFF   67584    // 512
#define CROW_OFF 68096    // 512
#define SR_OFF   68608    // 512
#define MRG_OFF  69120    // 512
#define CL_OFF   69632    // 128*CAP*4 = 12288 (doubles[512] overlay in finalize)
#define CC_OFF   81920    // 512
#define SLOT_OFF 82432    // 1024
#define WS_OFF   83456    // 64
#define SMEM_TOTAL 83520

__device__ __forceinline__ void imma16832(int d[4], const uint32_t a[4],
                                          uint32_t b0, uint32_t b1) {
    asm volatile(
        "mma.sync.aligned.m16n8k32.row.col.s32.s8.s8.s32 "
        "{%0,%1,%2,%3}, {%4,%5,%6,%7}, {%8,%9}, {%0,%1,%2,%3};"
        : "+r"(d[0]), "+r"(d[1]), "+r"(d[2]), "+r"(d[3])
        : "r"(a[0]), "r"(a[1]), "r"(a[2]), "r"(a[3]), "r"(b0), "r"(b1));
}

__device__ __forceinline__ uint32_t pack_s8x4(int v0, int v1, int v2, int v3) {
    return (uint32_t)(v0 & 255) | ((uint32_t)(v1 & 255) << 8) |
           ((uint32_t)(v2 & 255) << 16) | ((uint32_t)(v3 & 255) << 24);
}

// ---------------- prep1: resets + global max|e| -----------------------------
__global__ void vq_prep1(const float* __restrict__ emb) {
    const int k = blockIdx.x, t = threadIdx.x;
    if (t == 0) {
        g_counts[k] = 0u;
        if (k == 0) { g_loss_sum = 0.0; g_done = 0u; g_ticket = 0u; }
    }
    float a = fmaxf(fabsf(emb[k * DDIM + t]), fabsf(emb[k * DDIM + 32 + t]));
    #pragma unroll
    for (int o = 16; o > 0; o >>= 1)
        a = fmaxf(a, __shfl_xor_sync(0xffffffffu, a, o));
    if (t == 0) atomicMax(&g_maxE_bits, __float_as_uint(fmaxf(a, 1e-30f)));
}

// ---------------- prep2: exact ssq + uniform-scale s8 pack ------------------
__global__ void vq_prep2(const float* __restrict__ emb) {
    const int k = blockIdx.x, t = threadIdx.x;
    const float maxE = __uint_as_float(g_maxE_bits);
    const float sk = 127.f / maxE;
    const float S  = maxE * (1.f / 127.f);
    if (k == 0 && t == 0) g_S = S;
    if (t == 0) {
        const float* e = emb + k * DDIM;
        float s = 0.f;
        for (int d = 0; d < DDIM; d++)
            s = __fadd_rn(s, __fmul_rn(e[d], e[d]));   // reference order (unfused)
        ssq_g[k] = s;
    }
    int sabs = 0;
    if (t < 16) {
        int w = t >> 2, q = t & 3;
        int d0 = w * 16 + q * 4;
        int v[4];
        #pragma unroll
        for (int j = 0; j < 4; j++) {
            v[j] = __float2int_rn(emb[k * DDIM + d0 + j] * sk);
            sabs += abs(v[j]);
        }
        bpack_g[w >> 1][(k * 4 + q) * 2 + (w & 1)] = pack_s8x4(v[0], v[1], v[2], v[3]);
    }
    #pragma unroll
    for (int o = 16; o > 0; o >>= 1)
        sabs += __shfl_xor_sync(0xffffffffu, sabs, o);
    if (t == 0) atomicMax(&g_SeMax_bits, __float_as_uint((float)sabs * S));
}

// ---------------- exact rescue evaluation (bit-exact reference pipeline) ----
__device__ __forceinline__ void eval_exact(int k, int row, const float* emb,
                                           const float* x_s, const float* sx_s,
                                           const float* ssq_s, ull* slot) {
    const float4* eg = (const float4*)(emb + k * DDIM);
    float acc = 0.f;
    #pragma unroll
    for (int i = 0; i < 16; i++) {
        float4 e = eg[i];
        acc = fmaf(x_s[(4 * i + 0) * 128 + row], e.x, acc);
        acc = fmaf(x_s[(4 * i + 1) * 128 + row], e.y, acc);
        acc = fmaf(x_s[(4 * i + 2) * 128 + row], e.z, acc);
        acc = fmaf(x_s[(4 * i + 3) * 128 + row], e.w, acc);
    }
    float d = __fadd_rn(sx_s[row], ssq_s[k]);
    d = __fsub_rn(d, __fmul_rn(2.0f, acc));
    uint32_t ui = __float_as_uint(d);
    uint32_t key = ui ^ ((ui & 0x80000000u) ? 0xFFFFFFFFu : 0x80000000u);
    atomicMin(&slot[row], ((ull)key << 32) | (uint32_t)k);
}

// ---------------- main: persistent ticketed CTAs -----------------------------
extern __shared__ char smem[];

__global__ __launch_bounds__(THREADS, 2)
void vq_main_kernel(const float* __restrict__ z_e,
                    const float* __restrict__ emb,
                    float* __restrict__ zq_out,
                    float* __restrict__ idx_out,
                    float* __restrict__ loss_out,
                    float* __restrict__ perp_out)
{
    const int tid  = threadIdx.x;
    const int wid  = tid >> 5;
    const int lane = tid & 31;
    const int wq   = lane & 3;
    const int wr   = lane >> 2;

    float* x_s    = (float*)(smem + XS_OFF);
    float* ssq_s  = (float*)(smem + SSQ_OFF);
    float* sx_s   = (float*)(smem + SX_OFF);
    float* crow_s = (float*)(smem + CROW_OFF);
    float* sr_s   = (float*)(smem + SR_OFF);
    float* mrg_s  = (float*)(smem + MRG_OFF);
    uint32_t* clist = (uint32_t*)(smem + CL_OFF);
    uint32_t* ccnt  = (uint32_t*)(smem + CC_OFF);
    ull*   slot   = (ull*)(smem + SLOT_OFF);
    float* wsum   = (float*)(smem + WS_OFF);
    const uint32_t* sB0 = (const uint32_t*)(smem + B0_OFF);
    const uint32_t* sB1 = (const uint32_t*)(smem + B1_OFF);
    __shared__ unsigned s_tile;
    __shared__ int s_final;

    // Stage B (once per CTA) + per-code ssq
    {
        const uint4* g0 = (const uint4*)bpack_g[0];
        const uint4* g1 = (const uint4*)bpack_g[1];
        uint4* h0 = (uint4*)(smem + B0_OFF);
        uint4* h1 = (uint4*)(smem + B1_OFF);
        for (int i = tid; i < KNUM * 2; i += THREADS) { h0[i] = g0[i]; h1[i] = g1[i]; }
    }
    ssq_s[tid] = ssq_g[tid];
    if (tid == 0) s_final = 0;

    const float S     = g_S;
    const float SeMax = __uint_as_float(g_SeMax_bits);

    for (;;) {
        __syncthreads();
        if (tid == 0) s_tile = atomicAdd(&g_ticket, 1u);
        __syncthreads();
        const unsigned tile = s_tile;
        if (tile >= NTILES) break;

        const int n   = tile >> 5;
        const int hw0 = (tile & 31) * MTILE;
        const size_t gbase = (size_t)n * (DDIM * HW) + hw0;

        if (tid < MTILE) { slot[tid] = ~0ull; ccnt[tid] = 0u; }
        // x tile (coalesced) -> x_s[c*128+row]
        for (int i = tid; i < MTILE * DDIM; i += THREADS) {
            int c = i >> 7, r = i & 127;
            x_s[c * 128 + r] = z_e[gbase + (size_t)c * HW + r];
        }
        __syncthreads();

        // per-row: exact ||x||^2 (reference order) + max|x| + sum|x|
        if (tid < MTILE) {
            float s = 0.f, mx = 1e-30f, sa = 0.f;
            for (int c = 0; c < DDIM; c++) {
                float xv = x_s[c * 128 + tid];
                s = __fadd_rn(s, __fmul_rn(xv, xv));
                float av = fabsf(xv);
                mx = fmaxf(mx, av);
                sa += av;
            }
            sx_s[tid] = s;
            float srinv = mx * (1.f / 127.f);
            sr_s[tid]   = __fdividef(127.f, mx);
            crow_s[tid] = -2.f * S * srinv;
            mrg_s[tid]  = srinv * SeMax + S * sa + 5e-5f;
        }
        __syncthreads();

        // s8 A fragments for this warp's 16 rows (rA, rB)
        const int r0   = (wid & 7) * 16;
        const int half = wid >> 3;
        const int rA = r0 + wr, rB = rA + 8;
        const float srAq = sr_s[rA], srBq = sr_s[rB];
        uint32_t aq[2][4];
        #pragma unroll
        for (int kh = 0; kh < 2; kh++) {
            #pragma unroll
            for (int hh = 0; hh < 2; hh++) {
                int d0 = kh * 32 + hh * 16 + wq * 4;
                int vA[4], vB[4];
                #pragma unroll
                for (int j = 0; j < 4; j++) {
                    vA[j] = __float2int_rn(x_s[(d0 + j) * 128 + rA] * srAq);
                    vB[j] = __float2int_rn(x_s[(d0 + j) * 128 + rB] * srBq);
                }
                aq[kh][hh * 2 + 0] = pack_s8x4(vA[0], vA[1], vA[2], vA[3]);
                aq[kh][hh * 2 + 1] = pack_s8x4(vB[0], vB[1], vB[2], vB[3]);
            }
        }
        const float crowA = crow_s[rA], crowB = crow_s[rB];
        const float mrgA  = mrg_s[rA],  mrgB  = mrg_s[rB];

        // IMMA filter: 8 groups of 32 cols; dv = fmaf(I2F(acc), crow, ssq)
        float m0 = 3.4e38f, m1 = 3.4e38f;
        for (int g = 0; g < 8; g++) {
            int acc[4][4];
            #pragma unroll
            for (int nf = 0; nf < 4; nf++)
                #pragma unroll
                for (int j = 0; j < 4; j++) acc[nf][j] = 0;

            const int colbase0 = half * 256 + g * 32;
            #pragma unroll
            for (int nf = 0; nf < 4; nf++) {
                int bi = ((colbase0 + nf * 8 + wr) << 2) + wq;   // pair index
                uint2 p01 = *(const uint2*)(sB0 + bi * 2);       // LDS.64, conflict-free
                uint2 p23 = *(const uint2*)(sB1 + bi * 2);
                imma16832(acc[nf], aq[0], p01.x, p01.y);
                imma16832(acc[nf], aq[1], p23.x, p23.y);
            }
            float dv[4][4];
            #pragma unroll
            for (int nf = 0; nf < 4; nf++) {
                int c0 = colbase0 + nf * 8 + wq * 2;
                float2 sq = *(const float2*)(ssq_s + c0);
                dv[nf][0] = fmaf((float)acc[nf][0], crowA, sq.x);
                dv[nf][1] = fmaf((float)acc[nf][1], crowA, sq.y);
                dv[nf][2] = fmaf((float)acc[nf][2], crowB, sq.x);
                dv[nf][3] = fmaf((float)acc[nf][3], crowB, sq.y);
                m0 = fminf(m0, fminf(dv[nf][0], dv[nf][1]));
                m1 = fminf(m1, fminf(dv[nf][2], dv[nf][3]));
            }
            m0 = fminf(m0, __shfl_xor_sync(0xffffffffu, m0, 1));
            m0 = fminf(m0, __shfl_xor_sync(0xffffffffu, m0, 2));
            m1 = fminf(m1, __shfl_xor_sync(0xffffffffu, m1, 1));
            m1 = fminf(m1, __shfl_xor_sync(0xffffffffu, m1, 2));
            float t0 = m0 + mrgA, t1 = m1 + mrgB;
            #pragma unroll
            for (int nf = 0; nf < 4; nf++) {
                int c0 = colbase0 + nf * 8 + wq * 2;
                if (dv[nf][0] <= t0) { uint32_t c = atomicAdd(&ccnt[rA], 1u); if (c < CAP) clist[rA * CAP + c] = c0; }
                if (dv[nf][1] <= t0) { uint32_t c = atomicAdd(&ccnt[rA], 1u); if (c < CAP) clist[rA * CAP + c] = c0 + 1; }
                if (dv[nf][2] <= t1) { uint32_t c = atomicAdd(&ccnt[rB], 1u); if (c < CAP) clist[rB * CAP + c] = c0; }
                if (dv[nf][3] <= t1) { uint32_t c = atomicAdd(&ccnt[rB], 1u); if (c < CAP) clist[rB * CAP + c] = c0 + 1; }
            }
        }
        __syncthreads();

        // Rescue: exact re-evaluation (4 threads per row)
        {
            int row = tid >> 2, e0 = tid & 3;
            int cnt = (int)ccnt[row];
            if (cnt <= CAP) {
                for (int i = e0; i < cnt; i += 4)
                    eval_exact((int)clist[row * CAP + i], row, emb, x_s, sx_s, ssq_s, slot);
            } else {
                for (int k = e0; k < KNUM; k += 4)   // guaranteed-correct fallback
                    eval_exact(k, row, emb, x_s, sx_s, ssq_s, slot);
            }
        }
        __syncthreads();

        // Row-owned z_q straight-through (c-synchronized -> coalesced) + loss
        float lsum = 0.f;
        if (tid < MTILE) {
            const int r = tid;
            const int kk = (int)(uint32_t)(slot[r] & 0xFFFFFFFFull);
            if (idx_out) idx_out[tile * MTILE + r] = (float)kk;
            atomicAdd(&g_counts[kk], 1u);
            const float4* eg = (const float4*)(emb + kk * DDIM);
            #pragma unroll
            for (int i = 0; i < 16; i++) {
                float4 e = eg[i];
                #pragma unroll
                for (int j = 0; j < 4; j++) {
                    int c = 4 * i + j;
                    float v  = (j == 0) ? e.x : (j == 1) ? e.y : (j == 2) ? e.z : e.w;
                    float xv = x_s[c * 128 + r];
                    float diff = __fsub_rn(v, xv);
                    zq_out[gbase + (size_t)c * HW + r] = __fadd_rn(xv, diff);
                    lsum = fmaf(diff, diff, lsum);
                }
            }
        }
        #pragma unroll
        for (int o = 16; o > 0; o >>= 1)
            lsum += __shfl_down_sync(0xffffffffu, lsum, o);
        if (lane == 0 && wid < 4) wsum[wid] = lsum;
        __syncthreads();
        if (tid == 0) {
            float t = wsum[0] + wsum[1] + wsum[2] + wsum[3];
            atomicAdd(&g_loss_sum, (double)t);
            __threadfence();
            unsigned r = atomicAdd(&g_done, 1u);
            if (r == NTILES - 1) s_final = 1;
        }
    }

    // ---- fused finalize: the CTA that completed the last tile ----
    __syncthreads();
    if (s_final) {
        double* sh = (double*)(smem + CL_OFF);
        double c = (double)g_counts[tid];
        double p = c / (double)NROWS;
        sh[tid] = p * log(p + 1e-10);
        __syncthreads();
        for (int s = KNUM / 2; s > 0; s >>= 1) {
            if (tid < s) sh[tid] += sh[tid + s];
            __syncthreads();
        }
        if (tid == 0) {
            if (perp_out) *perp_out = (float)exp(-sh[0]);
            if (loss_out) *loss_out = (float)(0.25 * g_loss_sum / (double)((size_t)NROWS * DDIM));
        }
    }
}

extern "C" void kernel_launch(void* const* d_in, const int* in_sizes, int n_in,
                              void* d_out, int out_size) {
    const float* z_e = (const float*)d_in[0];
    const float* emb = (const float*)d_in[1];
    float* out = (float*)d_out;

    float* zq_out = out;
    float* loss_p = nullptr;
    float* perp_p = nullptr;
    float* idx_p  = nullptr;
    const int ZQ = NB * DDIM * HW;   // 4194304
    if (out_size >= ZQ + 2 + NROWS) {
        loss_p = out + ZQ;
        perp_p = out + ZQ + 1;
        idx_p  = out + ZQ + 2;
    }

    cudaFuncSetAttribute(vq_main_kernel,
                         cudaFuncAttributeMaxDynamicSharedMemorySize, SMEM_TOTAL);

    vq_prep1<<<KNUM, 32>>>(emb);
    vq_prep2<<<KNUM, 32>>>(emb);
    vq_main_kernel<<<GRID, THREADS, SMEM_TOTAL>>>(z_e, emb, zq_out, idx_p, loss_p, perp_p);
}